// round 17
// baseline (speedup 1.0000x reference)
#include <cuda_runtime.h>
#include <cuda_fp16.h>
#include <mma.h>
#include <cstdint>

using namespace nvcuda;

#define N_NODES 50000
#define N_EDGES 800000
#define CAP     64           // bucket slots per node; deg ~ Poisson(16), P(>64) ~ 1e-19

// ---------------- device scratch (allocation-free rule: __device__ globals) ----
__device__ float  g_dinv[N_NODES];
__device__ __align__(16) __half g_h  [N_NODES * 64];
__device__ __align__(16) float  g_x1 [N_NODES * 64];
__device__ __align__(16) float  g_x2 [N_NODES * 64];
__device__ int g_cnt   [N_NODES];
__device__ int g_bucket[N_NODES * CAP];

// ---------------- one-pass bucket fill: replaces count+scan+fill ----------------
__global__ void k_fill_bucket(const int* __restrict__ ei, int* cnt,
                              int* __restrict__ bucket) {
    int e = blockIdx.x * blockDim.x + threadIdx.x;
    if (e >= N_EDGES) return;
    int s = ei[e];
    int d = ei[N_EDGES + e];
    int pos = atomicAdd(&cnt[d], 1);
    if (pos < CAP) bucket[d * CAP + pos] = s;   // guard: never corrupt memory
}

// ------ tensor-core GEMM: H[N, DOUT] = X[N, 64] @ W[64, DOUT], fp16 out ---------
// wmma m16n16k16, fp16 inputs, fp32 accumulate. 8 warps x 16 rows = 128 rows/blk.
// 50000 % 16 == 0 -> warp tiles are fully in or fully out of range.
template <int DOUT, bool DINV>
__global__ void __launch_bounds__(256)
k_gemm(const float* __restrict__ X, const float* __restrict__ W,
       __half* __restrict__ H,
       const int* __restrict__ cnt, float* __restrict__ dinv) {
    constexpr int DIN  = 64;
    constexpr int ROWS = 128;
    constexpr int LDX  = DIN + 8;      // 72 (mult of 8 for wmma)
    constexpr int LDW  = DOUT + 8;     // 72 or 40
    __shared__ __align__(16) __half sX[ROWS * LDX];
    __shared__ __align__(16) __half sW[DIN * LDW];
    __shared__ __align__(16) float  sC[8][16 * 16];   // per-warp staging tile

    int tid  = threadIdx.x;
    int wid  = tid >> 5;
    int lane = tid & 31;
    int rowbase = blockIdx.x * ROWS;

    if (DINV && tid < ROWS) {
        int row = rowbase + tid;
        if (row < N_NODES) {
            int dg = cnt[row];
            if (dg > CAP) dg = CAP;
            dinv[row] = rsqrtf((float)dg + 1.0f);  // +1 self-loop
        }
    }

    // stage W as fp16 [k][n]
    for (int i = tid; i < DIN * DOUT; i += 256) {
        int k = i / DOUT;
        int n = i % DOUT;
        sW[k * LDW + n] = __float2half_rn(W[i]);
    }
    // stage X as fp16 [r][k] (coalesced float4 read)
    for (int i = tid; i < ROWS * (DIN / 4); i += 256) {
        int r = i / (DIN / 4);
        int q = i % (DIN / 4);
        int row = rowbase + r;
        float4 xv = (row < N_NODES)
            ? ((const float4*)X)[(size_t)row * (DIN / 4) + q]
            : make_float4(0.f, 0.f, 0.f, 0.f);
        __half2 h01 = __floats2half2_rn(xv.x, xv.y);
        __half2 h23 = __floats2half2_rn(xv.z, xv.w);
        *(__half2*)&sX[r * LDX + q * 4]     = h01;
        *(__half2*)&sX[r * LDX + q * 4 + 2] = h23;
    }
    __syncthreads();

    int r0   = wid * 16;
    int grow = rowbase + r0;
    if (grow >= N_NODES) return;   // tile-aligned: fully out of range

    wmma::fragment<wmma::accumulator, 16, 16, 16, float> facc[DOUT / 16];
#pragma unroll
    for (int t = 0; t < DOUT / 16; t++) wmma::fill_fragment(facc[t], 0.0f);

#pragma unroll
    for (int k = 0; k < DIN; k += 16) {
        wmma::fragment<wmma::matrix_a, 16, 16, 16, __half, wmma::row_major> fa;
        wmma::load_matrix_sync(fa, &sX[r0 * LDX + k], LDX);
#pragma unroll
        for (int t = 0; t < DOUT / 16; t++) {
            wmma::fragment<wmma::matrix_b, 16, 16, 16, __half, wmma::row_major> fb;
            wmma::load_matrix_sync(fb, &sW[k * LDW + t * 16], LDW);
            wmma::mma_sync(facc[t], fa, fb, facc[t]);
        }
    }

    // store via smem staging (no fragment-layout assumptions), fp16 out
    int rr = lane >> 1;          // 0..15
    int cc = (lane & 1) * 8;     // 0 or 8
#pragma unroll
    for (int t = 0; t < DOUT / 16; t++) {
        wmma::store_matrix_sync(sC[wid], facc[t], 16, wmma::mem_row_major);
        __syncwarp();
        const float* src = &sC[wid][rr * 16 + cc];
        __half2 o0 = __floats2half2_rn(src[0], src[1]);
        __half2 o1 = __floats2half2_rn(src[2], src[3]);
        __half2 o2 = __floats2half2_rn(src[4], src[5]);
        __half2 o3 = __floats2half2_rn(src[6], src[7]);
        uint4 u;
        u.x = *(unsigned*)&o0;
        u.y = *(unsigned*)&o1;
        u.z = *(unsigned*)&o2;
        u.w = *(unsigned*)&o3;
        *(uint4*)&H[(size_t)(grow + rr) * DOUT + t * 16 + cc] = u;
        __syncwarp();
    }
}

// ---- fused pull aggregation + self-loop + bias + activation --------------------
__device__ __forceinline__ void acc8(float4& acc, uint2 u, float w) {
    float2 f01 = __half22float2(*(__half2*)&u.x);
    float2 f23 = __half22float2(*(__half2*)&u.y);
    acc.x += f01.x * w;
    acc.y += f01.y * w;
    acc.z += f23.x * w;
    acc.w += f23.y * w;
}

template <int DOUT, bool TANH>
__global__ void k_agg(const int* __restrict__ cnt, const int* __restrict__ bucket,
                      const __half* __restrict__ H, const float* __restrict__ dinv,
                      const float* __restrict__ b, float* __restrict__ OUT) {
    constexpr int C   = DOUT / 4;
    constexpr int NPB = 256 / C;
    int lane = threadIdx.x % C;
    int node = blockIdx.x * NPB + threadIdx.x / C;
    if (node >= N_NODES) return;

    int end = cnt[node];
    if (end > CAP) end = CAP;
    const int* adj = &bucket[node * CAP];
    const uint2* H2 = (const uint2*)H;

    float4 acc = make_float4(0.f, 0.f, 0.f, 0.f);
    int e = 0;
    for (; e + 3 < end; e += 4) {
        int s0 = adj[e],     s1 = adj[e + 1];
        int s2 = adj[e + 2], s3 = adj[e + 3];
        uint2 u0 = H2[(size_t)s0 * C + lane];
        uint2 u1 = H2[(size_t)s1 * C + lane];
        uint2 u2 = H2[(size_t)s2 * C + lane];
        uint2 u3 = H2[(size_t)s3 * C + lane];
        float w0 = dinv[s0], w1 = dinv[s1], w2 = dinv[s2], w3 = dinv[s3];
        acc8(acc, u0, w0);
        acc8(acc, u1, w1);
        acc8(acc, u2, w2);
        acc8(acc, u3, w3);
    }
    for (; e < end; e++) {
        int s0 = adj[e];
        acc8(acc, H2[(size_t)s0 * C + lane], dinv[s0]);
    }

    float di = dinv[node];
    uint2 uh = H2[(size_t)node * C + lane];
    float2 h01 = __half22float2(*(__half2*)&uh.x);
    float2 h23 = __half22float2(*(__half2*)&uh.y);
    float4 bb = ((const float4*)b)[lane];
    float4 v;
    v.x = di * (acc.x + di * h01.x) + bb.x;
    v.y = di * (acc.y + di * h01.y) + bb.y;
    v.z = di * (acc.z + di * h23.x) + bb.z;
    v.w = di * (acc.w + di * h23.y) + bb.w;
    if (TANH) {
        v.x = tanhf(v.x); v.y = tanhf(v.y); v.z = tanhf(v.z); v.w = tanhf(v.w);
    }
    ((float4*)OUT)[(size_t)node * C + lane] = v;
}

// ---------------- launch --------------------------------------------------------
static inline int cdiv(long long a, int b) { return (int)((a + b - 1) / b); }

extern "C" void kernel_launch(void* const* d_in, const int* in_sizes, int n_in,
                              void* d_out, int out_size) {
    const float* x  = (const float*)d_in[0];
    const int*   ei = (const int*)d_in[1];      // JAX x64 disabled: int64 -> int32
    const float* W1 = (const float*)d_in[2];
    const float* b1 = (const float*)d_in[3];
    const float* W2 = (const float*)d_in[4];
    const float* b2 = (const float*)d_in[5];
    const float* W3 = (const float*)d_in[6];
    const float* b3 = (const float*)d_in[7];
    float*       out = (float*)d_out;

    float  *dinv, *x1, *x2;
    __half *h;
    int    *cnt, *bucket;
    cudaGetSymbolAddress((void**)&dinv,   g_dinv);
    cudaGetSymbolAddress((void**)&h,      g_h);
    cudaGetSymbolAddress((void**)&x1,     g_x1);
    cudaGetSymbolAddress((void**)&x2,     g_x2);
    cudaGetSymbolAddress((void**)&cnt,    g_cnt);
    cudaGetSymbolAddress((void**)&bucket, g_bucket);

    const int T = 256;

    // ---- adjacency build: zero counters + one-pass bucket fill ----
    cudaMemsetAsync(cnt, 0, N_NODES * sizeof(int));
    k_fill_bucket<<<cdiv(N_EDGES, T), T>>>(ei, cnt, bucket);

    // ---- layer 1: x -> x1 (tanh); gemm also derives dinv from cnt ----
    k_gemm<64, true><<<cdiv(N_NODES, 128), T>>>(x, W1, h, cnt, dinv);
    k_agg<64, true><<<cdiv(N_NODES * 16, T), T>>>(cnt, bucket, h, dinv, b1, x1);

    // ---- layer 2: x1 -> x2 (tanh) ----
    k_gemm<64, false><<<cdiv(N_NODES, 128), T>>>(x1, W2, h, cnt, dinv);
    k_agg<64, true><<<cdiv(N_NODES * 16, T), T>>>(cnt, bucket, h, dinv, b2, x2);

    // ---- layer 3: x2 -> out (linear) ----
    k_gemm<32, false><<<cdiv(N_NODES, 128), T>>>(x2, W3, h, cnt, dinv);
    k_agg<32, false><<<cdiv(N_NODES * 8, T), T>>>(cnt, bucket, h, dinv, b3, out);
}